// round 16
// baseline (speedup 1.0000x reference)
#include <cuda_runtime.h>
#include <cuda_bf16.h>

#define MARGIN 0.4f

// FINAL KERNEL (R10 optimum; reproduced at 39.42 us in R10, R13, R15).
//
// 625 blocks x 320 threads (10 warps). Block b owns the contiguous rows
// [b*800, (b+1)*800) = 400 KB. 10 iterations x (10 warps x 8 rows) = 800.
//
// Prefetch schedule (empirically optimal; all perturbations regressed:
// dist 3 + prologue -8.4us, startup chunk-1 -2.2us, 2x20KB split -0.3us,
// no prefetch -4.1us): one 40 KB cp.async.bulk.prefetch.L2 per block per
// iteration at distance 2. The bulk engine is decoupled from warp
// scheduling and keeps the DRAM queue smoothly fed, lifting the stream
// from 6.0 TB/s (demand-load ceiling) to ~6.5 TB/s.
#define BLOCKS  625
#define THREADS 320
#define WARPS_PER_BLOCK (THREADS / 32)
#define ROWS_PER_ITER   (WARPS_PER_BLOCK * 8)   // 80 rows = 40 KB
#define PF_DIST 2                                // prefetch 2 chunks ahead

// Device-global scratch (no allocations allowed anywhere).
__device__ float        g_acc     = 0.0f;
__device__ unsigned int g_counter = 0u;

// Bulk DRAM->L2 prefetch via the async/bulk engine.
__device__ __forceinline__ void prefetch_l2_bulk(const void* gaddr, unsigned bytes) {
    asm volatile("cp.async.bulk.prefetch.L2.global [%0], %1;"
                 :: "l"(gaddr), "r"(bytes) : "memory");
}

__global__ void __launch_bounds__(THREADS, 5)
tl_fused_kernel(const float* __restrict__ anchor,
                const float* __restrict__ positive,
                const float* __restrict__ negatives,
                float* __restrict__ out,
                int N) {
    const int lane = threadIdx.x & 31;
    const int warp_in_block = threadIdx.x >> 5;

    // Anchor slice in registers (lane*16B covers D=128 across the warp).
    const float4 av = reinterpret_cast<const float4*>(anchor)[lane];

    float base;
    {
        const float4 pv = reinterpret_cast<const float4*>(positive)[lane];
        float s = av.x * pv.x + av.y * pv.y + av.z * pv.z + av.w * pv.w;
        #pragma unroll
        for (int o = 16; o > 0; o >>= 1)
            s += __shfl_xor_sync(0xffffffffu, s, o);
        base = s + MARGIN;   // identical in all lanes
    }

    const float4* __restrict__ neg4 = reinterpret_cast<const float4*>(negatives);
    const bool group_leader = ((lane & 3) == 0);

    float sum = 0.0f;

    // Contiguous per-block partition.
    const int rows_per_block = N / gridDim.x;          // 800 for this problem
    const int block_base     = blockIdx.x * rows_per_block;
    const int n_iters        = rows_per_block / ROWS_PER_ITER;  // 10

    // Warp's first row of iteration i: block_base + i*80 + warp*8.
    const float4* p = neg4 + (size_t)(block_base + warp_in_block * 8) * 32 + lane;
    const long long pstep = (long long)ROWS_PER_ITER * 32;

    #pragma unroll 1
    for (int it = 0; it < n_iters; it++, p += pstep) {
        // One thread per block streams the chunk PF_DIST iterations ahead
        // into L2 via the bulk engine (dense, scheduler-independent).
        if (threadIdx.x == 0 && it + PF_DIST < n_iters) {
            const float* pf = negatives
                + (size_t)(block_base + (it + PF_DIST) * ROWS_PER_ITER) * 128;
            prefetch_l2_bulk(pf, ROWS_PER_ITER * 512u);   // 40 KB
        }

        // 8 front-batched streaming LDG.128.
        float4 v0 = __ldcs(p + 0 * 32);
        float4 v1 = __ldcs(p + 1 * 32);
        float4 v2 = __ldcs(p + 2 * 32);
        float4 v3 = __ldcs(p + 3 * 32);
        float4 v4 = __ldcs(p + 4 * 32);
        float4 v5 = __ldcs(p + 5 * 32);
        float4 v6 = __ldcs(p + 6 * 32);
        float4 v7 = __ldcs(p + 7 * 32);

        float s0 = av.x * v0.x + av.y * v0.y + av.z * v0.z + av.w * v0.w;
        float s1 = av.x * v1.x + av.y * v1.y + av.z * v1.z + av.w * v1.w;
        float s2 = av.x * v2.x + av.y * v2.y + av.z * v2.z + av.w * v2.w;
        float s3 = av.x * v3.x + av.y * v3.y + av.z * v3.z + av.w * v3.w;
        float s4 = av.x * v4.x + av.y * v4.y + av.z * v4.z + av.w * v4.w;
        float s5 = av.x * v5.x + av.y * v5.y + av.z * v5.z + av.w * v5.w;
        float s6 = av.x * v6.x + av.y * v6.y + av.z * v6.z + av.w * v6.w;
        float s7 = av.x * v7.x + av.y * v7.y + av.z * v7.z + av.w * v7.w;

        // 8-row merge-tree reduction: 9 SHFL per 8 rows.
        const bool b4 = (lane & 16) != 0;
        float c0 = (b4 ? s1 : s0) + __shfl_xor_sync(0xffffffffu, b4 ? s0 : s1, 16);
        float c1 = (b4 ? s3 : s2) + __shfl_xor_sync(0xffffffffu, b4 ? s2 : s3, 16);
        float c2 = (b4 ? s5 : s4) + __shfl_xor_sync(0xffffffffu, b4 ? s4 : s5, 16);
        float c3 = (b4 ? s7 : s6) + __shfl_xor_sync(0xffffffffu, b4 ? s6 : s7, 16);

        const bool b3 = (lane & 8) != 0;
        float d0 = (b3 ? c1 : c0) + __shfl_xor_sync(0xffffffffu, b3 ? c0 : c1, 8);
        float d1 = (b3 ? c3 : c2) + __shfl_xor_sync(0xffffffffu, b3 ? c2 : c3, 8);

        const bool b2 = (lane & 4) != 0;
        float e = (b2 ? d1 : d0) + __shfl_xor_sync(0xffffffffu, b2 ? d0 : d1, 4);

        e += __shfl_xor_sync(0xffffffffu, e, 2);
        e += __shfl_xor_sync(0xffffffffu, e, 1);

        float rl = fmaxf(base - e, 0.0f);
        sum += group_leader ? rl : 0.0f;
    }

    // Safety tail for any rows not covered by the uniform partition
    // (none for N=500000 with 625 blocks, but keep correctness general).
    {
        int covered = gridDim.x * rows_per_block;   // == N here
        int r = covered + blockIdx.x * WARPS_PER_BLOCK + warp_in_block;
        #pragma unroll 1
        for (; r < N; r += gridDim.x * WARPS_PER_BLOCK) {
            float4 v = __ldcs(neg4 + (size_t)r * 32 + lane);
            float s = av.x * v.x + av.y * v.y + av.z * v.z + av.w * v.w;
            #pragma unroll
            for (int o = 16; o > 0; o >>= 1)
                s += __shfl_xor_sync(0xffffffffu, s, o);
            if (lane == 0) sum += fmaxf(base - s, 0.0f);
        }
    }

    // Full warp reduce of per-lane sums.
    #pragma unroll
    for (int o = 16; o > 0; o >>= 1)
        sum += __shfl_xor_sync(0xffffffffu, sum, o);

    // Block reduce -> one atomicAdd per block -> last block finalizes.
    __shared__ float warp_sums[WARPS_PER_BLOCK];
    if (lane == 0) warp_sums[warp_in_block] = sum;
    __syncthreads();

    if (threadIdx.x == 0) {
        float bsum = 0.0f;
        #pragma unroll
        for (int w = 0; w < WARPS_PER_BLOCK; w++) bsum += warp_sums[w];
        atomicAdd(&g_acc, bsum);
        __threadfence();
        unsigned int ticket = atomicInc(&g_counter, gridDim.x - 1);
        if (ticket == gridDim.x - 1) {
            float total = *((volatile float*)&g_acc);
            out[0] = total / (float)N;
            *((volatile float*)&g_acc) = 0.0f;   // reset for next graph replay
        }
    }
}

extern "C" void kernel_launch(void* const* d_in, const int* in_sizes, int n_in,
                              void* d_out, int out_size) {
    const float* anchor    = (const float*)d_in[0];
    const float* positive  = (const float*)d_in[1];
    const float* negatives = (const float*)d_in[2];
    float* out = (float*)d_out;

    const int D = 128;
    const int N = in_sizes[2] / D;  // 500000

    tl_fused_kernel<<<BLOCKS, THREADS>>>(anchor, positive, negatives, out, N);
}

// round 17
// speedup vs baseline: 1.1212x; 1.1212x over previous
#include <cuda_runtime.h>
#include <cuda_bf16.h>

#define MARGIN 0.4f

// R17 variant of the R10 optimum: finer prefetch tiling via grid shape.
// 1250 blocks x 160 threads (5 warps). Block b owns contiguous rows
// [b*400, (b+1)*400) = 200 KB. 10 iterations x (5 warps x 8 rows) = 400.
// One 20 KB cp.async.bulk.prefetch.L2 per block per iteration, distance 2
// (same schedule as the proven optimum, half the chunk size, 2x the
// independent block streams).
#define BLOCKS  1250
#define THREADS 160
#define WARPS_PER_BLOCK (THREADS / 32)           // 5
#define ROWS_PER_ITER   (WARPS_PER_BLOCK * 8)    // 40 rows = 20 KB
#define PF_DIST 2                                 // prefetch 2 chunks ahead

// Device-global scratch (no allocations allowed anywhere).
__device__ float        g_acc     = 0.0f;
__device__ unsigned int g_counter = 0u;

// Bulk DRAM->L2 prefetch via the async/bulk engine.
__device__ __forceinline__ void prefetch_l2_bulk(const void* gaddr, unsigned bytes) {
    asm volatile("cp.async.bulk.prefetch.L2.global [%0], %1;"
                 :: "l"(gaddr), "r"(bytes) : "memory");
}

__global__ void __launch_bounds__(THREADS, 9)
tl_fused_kernel(const float* __restrict__ anchor,
                const float* __restrict__ positive,
                const float* __restrict__ negatives,
                float* __restrict__ out,
                int N) {
    const int lane = threadIdx.x & 31;
    const int warp_in_block = threadIdx.x >> 5;

    // Anchor slice in registers (lane*16B covers D=128 across the warp).
    const float4 av = reinterpret_cast<const float4*>(anchor)[lane];

    float base;
    {
        const float4 pv = reinterpret_cast<const float4*>(positive)[lane];
        float s = av.x * pv.x + av.y * pv.y + av.z * pv.z + av.w * pv.w;
        #pragma unroll
        for (int o = 16; o > 0; o >>= 1)
            s += __shfl_xor_sync(0xffffffffu, s, o);
        base = s + MARGIN;   // identical in all lanes
    }

    const float4* __restrict__ neg4 = reinterpret_cast<const float4*>(negatives);
    const bool group_leader = ((lane & 3) == 0);

    float sum = 0.0f;

    // Contiguous per-block partition.
    const int rows_per_block = N / gridDim.x;          // 400 for this problem
    const int block_base     = blockIdx.x * rows_per_block;
    const int n_iters        = rows_per_block / ROWS_PER_ITER;  // 10

    // Warp's first row of iteration i: block_base + i*40 + warp*8.
    const float4* p = neg4 + (size_t)(block_base + warp_in_block * 8) * 32 + lane;
    const long long pstep = (long long)ROWS_PER_ITER * 32;

    #pragma unroll 1
    for (int it = 0; it < n_iters; it++, p += pstep) {
        // One thread per block streams the chunk PF_DIST iterations ahead
        // into L2 via the bulk engine (dense, scheduler-independent).
        if (threadIdx.x == 0 && it + PF_DIST < n_iters) {
            const float* pf = negatives
                + (size_t)(block_base + (it + PF_DIST) * ROWS_PER_ITER) * 128;
            prefetch_l2_bulk(pf, ROWS_PER_ITER * 512u);   // 20 KB
        }

        // 8 front-batched streaming LDG.128.
        float4 v0 = __ldcs(p + 0 * 32);
        float4 v1 = __ldcs(p + 1 * 32);
        float4 v2 = __ldcs(p + 2 * 32);
        float4 v3 = __ldcs(p + 3 * 32);
        float4 v4 = __ldcs(p + 4 * 32);
        float4 v5 = __ldcs(p + 5 * 32);
        float4 v6 = __ldcs(p + 6 * 32);
        float4 v7 = __ldcs(p + 7 * 32);

        float s0 = av.x * v0.x + av.y * v0.y + av.z * v0.z + av.w * v0.w;
        float s1 = av.x * v1.x + av.y * v1.y + av.z * v1.z + av.w * v1.w;
        float s2 = av.x * v2.x + av.y * v2.y + av.z * v2.z + av.w * v2.w;
        float s3 = av.x * v3.x + av.y * v3.y + av.z * v3.z + av.w * v3.w;
        float s4 = av.x * v4.x + av.y * v4.y + av.z * v4.z + av.w * v4.w;
        float s5 = av.x * v5.x + av.y * v5.y + av.z * v5.z + av.w * v5.w;
        float s6 = av.x * v6.x + av.y * v6.y + av.z * v6.z + av.w * v6.w;
        float s7 = av.x * v7.x + av.y * v7.y + av.z * v7.z + av.w * v7.w;

        // 8-row merge-tree reduction: 9 SHFL per 8 rows.
        const bool b4 = (lane & 16) != 0;
        float c0 = (b4 ? s1 : s0) + __shfl_xor_sync(0xffffffffu, b4 ? s0 : s1, 16);
        float c1 = (b4 ? s3 : s2) + __shfl_xor_sync(0xffffffffu, b4 ? s2 : s3, 16);
        float c2 = (b4 ? s5 : s4) + __shfl_xor_sync(0xffffffffu, b4 ? s4 : s5, 16);
        float c3 = (b4 ? s7 : s6) + __shfl_xor_sync(0xffffffffu, b4 ? s6 : s7, 16);

        const bool b3 = (lane & 8) != 0;
        float d0 = (b3 ? c1 : c0) + __shfl_xor_sync(0xffffffffu, b3 ? c0 : c1, 8);
        float d1 = (b3 ? c3 : c2) + __shfl_xor_sync(0xffffffffu, b3 ? c2 : c3, 8);

        const bool b2 = (lane & 4) != 0;
        float e = (b2 ? d1 : d0) + __shfl_xor_sync(0xffffffffu, b2 ? d0 : d1, 4);

        e += __shfl_xor_sync(0xffffffffu, e, 2);
        e += __shfl_xor_sync(0xffffffffu, e, 1);

        float rl = fmaxf(base - e, 0.0f);
        sum += group_leader ? rl : 0.0f;
    }

    // Safety tail for any rows not covered by the uniform partition
    // (none for N=500000 with 1250 blocks, but keep correctness general).
    {
        int covered = gridDim.x * rows_per_block;   // == N here
        int r = covered + blockIdx.x * WARPS_PER_BLOCK + warp_in_block;
        #pragma unroll 1
        for (; r < N; r += gridDim.x * WARPS_PER_BLOCK) {
            float4 v = __ldcs(neg4 + (size_t)r * 32 + lane);
            float s = av.x * v.x + av.y * v.y + av.z * v.z + av.w * v.w;
            #pragma unroll
            for (int o = 16; o > 0; o >>= 1)
                s += __shfl_xor_sync(0xffffffffu, s, o);
            if (lane == 0) sum += fmaxf(base - s, 0.0f);
        }
    }

    // Full warp reduce of per-lane sums.
    #pragma unroll
    for (int o = 16; o > 0; o >>= 1)
        sum += __shfl_xor_sync(0xffffffffu, sum, o);

    // Block reduce -> one atomicAdd per block -> last block finalizes.
    __shared__ float warp_sums[WARPS_PER_BLOCK];
    if (lane == 0) warp_sums[warp_in_block] = sum;
    __syncthreads();

    if (threadIdx.x == 0) {
        float bsum = 0.0f;
        #pragma unroll
        for (int w = 0; w < WARPS_PER_BLOCK; w++) bsum += warp_sums[w];
        atomicAdd(&g_acc, bsum);
        __threadfence();
        unsigned int ticket = atomicInc(&g_counter, gridDim.x - 1);
        if (ticket == gridDim.x - 1) {
            float total = *((volatile float*)&g_acc);
            out[0] = total / (float)N;
            *((volatile float*)&g_acc) = 0.0f;   // reset for next graph replay
        }
    }
}

extern "C" void kernel_launch(void* const* d_in, const int* in_sizes, int n_in,
                              void* d_out, int out_size) {
    const float* anchor    = (const float*)d_in[0];
    const float* positive  = (const float*)d_in[1];
    const float* negatives = (const float*)d_in[2];
    float* out = (float*)d_out;

    const int D = 128;
    const int N = in_sizes[2] / D;  // 500000

    tl_fused_kernel<<<BLOCKS, THREADS>>>(anchor, positive, negatives, out, N);
}